// round 9
// baseline (speedup 1.0000x reference)
#include <cuda_runtime.h>
#include <cuda_bf16.h>
#include <cuda_fp16.h>

#define H     128
#define BATCH 8
#define TQ    512
#define TK    512

// Device scratch (allocation-free rule: __device__ globals)
__device__ __align__(16) __half2 g_qph[BATCH * TQ * (H/2)];    // [b][q][h/2] packed h-pairs
__device__ __align__(16) __half2 g_kph[BATCH * (H/2) * TK];    // [b][h/2][k] packed h-pairs

__device__ __forceinline__ __half2 tanh2(__half2 x) {
    unsigned xi = *(unsigned*)&x, yi;
    asm("tanh.approx.f16x2 %0, %1;" : "=r"(yi) : "r"(xi));
    return *(__half2*)&yi;
}

// ---------------------------------------------------------------------------
// Kernel 1: projections, micro-GEMM with smem-transposed W chunks.
//   proj==0:  g_qph[b][t][h/2] = queries @ Wa_w^T + Wa_b  (half2 h-pairs, q-major)
//   proj==1:  g_kph[b][h/2][t] = keys    @ Ua_w^T + Ua_b  (half2 h-pairs, k-major)
// grid = (T/16, B, 2), block = 128. Thread (t = tid>>3, g = tid&7) computes
// rows t, output cols h = 32c + 4g .. 4g+3 over 4 chunks c.
// ---------------------------------------------------------------------------
__global__ void __launch_bounds__(128) proj_kernel(
    const float* __restrict__ queries, const float* __restrict__ keys,
    const float* __restrict__ Wa_w, const float* __restrict__ Wa_b,
    const float* __restrict__ Ua_w, const float* __restrict__ Ua_b)
{
    const int tile = blockIdx.x;   // 32 tiles of 16 rows
    const int b    = blockIdx.y;
    const int proj = blockIdx.z;

    const float* x    = proj == 0 ? queries : keys;
    const float* W    = proj == 0 ? Wa_w    : Ua_w;
    const float* bias = proj == 0 ? Wa_b    : Ua_b;

    const int t0 = tile * 16;
    __shared__ __align__(16) float xs[16][H];     // 8 KB
    __shared__ __align__(16) float Wt[H][36];     // 18 KB, Wt[k][h_local], pad 36

    // Stage x tile (coalesced)
    const float4* xsrc = (const float4*)(x + (size_t)(b * 512 + t0) * H);
    #pragma unroll
    for (int i = threadIdx.x; i < 16 * H / 4; i += 128)
        ((float4*)xs)[i] = xsrc[i];

    const int t = threadIdx.x >> 3;    // row 0..15
    const int g = threadIdx.x & 7;     // h-group -> h_local = 4g..4g+3

    #pragma unroll 1
    for (int c = 0; c < 4; c++) {
        __syncthreads();   // xs ready (c=0) / previous Wt consumed
        // Stage W rows [32c, 32c+32) transposed: coalesced LDG.128
        const float4* wsrc = (const float4*)(W + (size_t)(32 * c) * H);
        #pragma unroll
        for (int r = 0; r < 8; r++) {
            int f4 = threadIdx.x + 128 * r;   // 0..1023
            int hl = f4 >> 5;                 // 0..31 (row within chunk)
            int k4 = f4 & 31;
            float4 v = wsrc[f4];
            Wt[4*k4+0][hl] = v.x;
            Wt[4*k4+1][hl] = v.y;
            Wt[4*k4+2][hl] = v.z;
            Wt[4*k4+3][hl] = v.w;
        }
        __syncthreads();

        float a0 = 0.f, a1 = 0.f, a2 = 0.f, a3 = 0.f;
        #pragma unroll 8
        for (int k = 0; k < H; k++) {
            float  xv = xs[t][k];                          // 4-addr broadcast LDS
            float4 wv = *(const float4*)&Wt[k][4 * g];     // conflict-free LDS.128
            a0 = fmaf(xv, wv.x, a0);
            a1 = fmaf(xv, wv.y, a1);
            a2 = fmaf(xv, wv.z, a2);
            a3 = fmaf(xv, wv.w, a3);
        }
        float4 bv = *(const float4*)(bias + 32 * c + 4 * g);
        __half2 p0 = __floats2half2_rn(a0 + bv.x, a1 + bv.y);
        __half2 p1 = __floats2half2_rn(a2 + bv.z, a3 + bv.w);
        const int j = 16 * c + 2 * g;      // h-pair index (even)

        if (proj == 0) {
            uint2 pp = make_uint2(*(unsigned*)&p0, *(unsigned*)&p1);
            *(uint2*)(g_qph + ((size_t)(b * TQ + t0 + t) * (H/2) + j)) = pp;
        } else {
            g_kph[(size_t)b * (H/2) * TK + (size_t)j       * TK + t0 + t] = p0;
            g_kph[(size_t)b * (H/2) * TK + (size_t)(j + 1) * TK + t0 + t] = p1;
        }
    }
}

// ---------------------------------------------------------------------------
// Kernel 2: scores + softmax (best-measured round-6 structure, direct LDG).
// grid (TQ/4, B), block 128 (4 warps, 1 q/warp). Lane owns keys {64t+2lane+e}.
// Datapath: HADD2 -> tanh.f16x2 (MUFU) -> HFMA2; f32 flush every 8 h-pairs.
// ---------------------------------------------------------------------------
__global__ void __launch_bounds__(128) score_kernel(
    const float* __restrict__ Va_w,
    float* __restrict__ w_out)     // (B, TQ, TK)
{
    __shared__ __align__(8) float2 qm[4][H/2];   // per warp: {q2 bits, va2 bits}

    const int b    = blockIdx.y;
    const int wid  = threadIdx.x >> 5;
    const int lane = threadIdx.x & 31;
    const int q    = blockIdx.x * 4 + wid;

    {
        // q already half2-packed by proj: j = 2*lane, 2*lane+1
        uint2 qq = ((const uint2*)(g_qph + (size_t)(b * TQ + q) * (H/2)))[lane];
        float4 vv = ((const float4*)Va_w)[lane];     // Va[4lane .. 4lane+3]
        __half2 va0 = __floats2half2_rn(vv.x, vv.y);
        __half2 va1 = __floats2half2_rn(vv.z, vv.w);
        qm[wid][2*lane]   = make_float2(__uint_as_float(qq.x),
                                        __uint_as_float(*(unsigned*)&va0));
        qm[wid][2*lane+1] = make_float2(__uint_as_float(qq.y),
                                        __uint_as_float(*(unsigned*)&va1));
    }
    __syncwarp();

    float a[16];
    #pragma unroll
    for (int i = 0; i < 16; i++) a[i] = 0.f;

    const uint2* kb = (const uint2*)(g_kph + (size_t)b * (H/2) * TK) + lane;

    #pragma unroll 1
    for (int jb = 0; jb < 8; jb++) {           // 8 blocks of 8 h-pairs
        __half2 acc2[16];
        #pragma unroll
        for (int i = 0; i < 16; i++) acc2[i] = __half2half2(__float2half(0.f));

        #pragma unroll
        for (int j2 = 0; j2 < 8; j2++) {
            int j = jb * 8 + j2;
            float2 meta = qm[wid][j];          // broadcast LDS.64
            unsigned qb = __float_as_uint(meta.x);
            unsigned vb = __float_as_uint(meta.y);
            __half2 q2  = *(__half2*)&qb;
            __half2 va2 = *(__half2*)&vb;

            const uint2* kr = kb + j * (TK / 2);
            uint2 kk[8];
            #pragma unroll
            for (int t = 0; t < 8; t++) kk[t] = kr[t * 32];   // MLP=8 LDG.64
            #pragma unroll
            for (int t = 0; t < 8; t++) {
                __half2 k0 = *(__half2*)&kk[t].x;
                __half2 k1 = *(__half2*)&kk[t].y;
                acc2[2*t]   = __hfma2(va2, tanh2(__hadd2(q2, k0)), acc2[2*t]);
                acc2[2*t+1] = __hfma2(va2, tanh2(__hadd2(q2, k1)), acc2[2*t+1]);
            }
        }
        #pragma unroll
        for (int i = 0; i < 16; i++) {
            float2 f = __half22float2(acc2[i]);
            a[i] += f.x + f.y;                 // fold even/odd-h partial sums
        }
    }

    // ---- softmax in registers ----
    float m = a[0];
    #pragma unroll
    for (int i = 1; i < 16; i++) m = fmaxf(m, a[i]);
    #pragma unroll
    for (int o = 16; o > 0; o >>= 1)
        m = fmaxf(m, __shfl_xor_sync(0xffffffffu, m, o));

    float s = 0.f;
    #pragma unroll
    for (int i = 0; i < 16; i++) { a[i] = __expf(a[i] - m); s += a[i]; }
    #pragma unroll
    for (int o = 16; o > 0; o >>= 1)
        s += __shfl_xor_sync(0xffffffffu, s, o);

    const float inv = __fdividef(1.f, s);
    float* wrow = w_out + (size_t)(b * TQ + q) * TK;
    #pragma unroll
    for (int t = 0; t < 8; t++)
        *(float2*)(wrow + 64 * t + 2 * lane) =
            make_float2(a[2*t] * inv, a[2*t+1] * inv);
}

// ---------------------------------------------------------------------------
// Kernel 3: context = w @ keys. grid (TQ/16, B), block 256 (8 warps, 16 q).
// Keys staged in smem chunks shared by all 8 warps -> L2 traffic halved
// vs per-warp streaming; conflict-free LDS.128 in the hot loop.
// ---------------------------------------------------------------------------
__global__ void __launch_bounds__(256) ctx_kernel(
    const float* __restrict__ keys,
    const float* __restrict__ w_in,    // (B, TQ, TK)
    float* __restrict__ ctx_out)       // (B, TQ, H)
{
    __shared__ float  wsm[16][TK];     // 32 KB weights
    __shared__ __align__(16) float4 skv[32 * 32];   // 16 KB: 32 keys x 128 floats

    const int b    = blockIdx.y;
    const int wid  = threadIdx.x >> 5;
    const int lane = threadIdx.x & 31;
    const int q0   = blockIdx.x * 16 + 2 * wid;

    {   // each warp stages its own 2 weight rows (coalesced)
        const float4* src = (const float4*)(w_in + (size_t)(b * TQ + q0) * TK);
        float4* dst = (float4*)&wsm[2 * wid][0];
        #pragma unroll
        for (int i = 0; i < 8; i++)
            dst[lane + 32 * i] = src[lane + 32 * i];
    }

    float4 acc0 = make_float4(0.f, 0.f, 0.f, 0.f);
    float4 acc1 = make_float4(0.f, 0.f, 0.f, 0.f);
    const float4* ksrc4 = (const float4*)(keys + (size_t)b * TK * H);
    const float* w0 = wsm[2 * wid];
    const float* w1 = wsm[2 * wid + 1];

    #pragma unroll 1
    for (int c = 0; c < 16; c++) {             // 16 chunks of 32 keys
        __syncthreads();                       // prev chunk consumed (+ wsm on c=0)
        #pragma unroll
        for (int r = 0; r < 4; r++) {
            int idx = threadIdx.x + 256 * r;   // 0..1023
            skv[idx] = ksrc4[c * 1024 + idx];
        }
        __syncthreads();

        #pragma unroll 8
        for (int kk = 0; kk < 32; kk++) {
            float4 kv = skv[kk * 32 + lane];   // conflict-free LDS.128
            float  wa = w0[32 * c + kk];       // broadcast LDS
            float  wb = w1[32 * c + kk];
            acc0.x = fmaf(wa, kv.x, acc0.x); acc0.y = fmaf(wa, kv.y, acc0.y);
            acc0.z = fmaf(wa, kv.z, acc0.z); acc0.w = fmaf(wa, kv.w, acc0.w);
            acc1.x = fmaf(wb, kv.x, acc1.x); acc1.y = fmaf(wb, kv.y, acc1.y);
            acc1.z = fmaf(wb, kv.z, acc1.z); acc1.w = fmaf(wb, kv.w, acc1.w);
        }
    }
    float4* crow = (float4*)(ctx_out + (size_t)(b * TQ + q0) * H);
    crow[lane]           = acc0;
    crow[lane + (H / 4)] = acc1;
}

// ---------------------------------------------------------------------------
extern "C" void kernel_launch(void* const* d_in, const int* in_sizes, int n_in,
                              void* d_out, int out_size)
{
    const float* queries = (const float*)d_in[0];
    const float* keys    = (const float*)d_in[1];
    const float* Wa_w    = (const float*)d_in[2];
    const float* Wa_b    = (const float*)d_in[3];
    const float* Ua_w    = (const float*)d_in[4];
    const float* Ua_b    = (const float*)d_in[5];
    const float* Va_w    = (const float*)d_in[6];
    // Va bias (d_in[7]) cancels in softmax -> unused.

    float* ctx_out = (float*)d_out;                     // (B, TQ, H)
    float* w_out   = ctx_out + BATCH * TQ * H;          // (B, TQ, TK)

    dim3 g1(512 / 16, BATCH, 2);
    proj_kernel<<<g1, 128>>>(queries, keys, Wa_w, Wa_b, Ua_w, Ua_b);

    dim3 g2(TQ / 4, BATCH);
    score_kernel<<<g2, 128>>>(Va_w, w_out);

    dim3 g3(TQ / 16, BATCH);
    ctx_kernel<<<g3, 256>>>(keys, w_out, ctx_out);
}

// round 10
// speedup vs baseline: 1.1863x; 1.1863x over previous
#include <cuda_runtime.h>
#include <cuda_bf16.h>
#include <cuda_fp16.h>

#define H     128
#define BATCH 8
#define TQ    512
#define TK    512

// Device scratch (allocation-free rule: __device__ globals)
__device__ __align__(16) float   g_qp [BATCH * TQ * H];        // [b][q][h] f32
__device__ __align__(16) __half2 g_kph[BATCH * (H/2) * TK];    // [b][h/2][k] packed h-pairs

__device__ __forceinline__ __half2 tanh2(__half2 x) {
    unsigned xi = *(unsigned*)&x, yi;
    asm("tanh.approx.f16x2 %0, %1;" : "=r"(yi) : "r"(xi));
    return *(__half2*)&yi;
}

// ---------------------------------------------------------------------------
// Kernel 1: projections (round-6 structure — best measured: 21.7us).
//   proj==0:  g_qp[b][t][h]    = queries @ Wa_w^T + Wa_b   (f32)
//   proj==1:  g_kph[b][h/2][t] = keys    @ Ua_w^T + Ua_b   (half2 h-pairs)
// grid = (T/16, B, 2), block = 128 (one thread per output column h)
// ---------------------------------------------------------------------------
__global__ void __launch_bounds__(128) proj_kernel(
    const float* __restrict__ queries, const float* __restrict__ keys,
    const float* __restrict__ Wa_w, const float* __restrict__ Wa_b,
    const float* __restrict__ Ua_w, const float* __restrict__ Ua_b)
{
    const int tile = blockIdx.x;   // 32 tiles of 16 rows
    const int b    = blockIdx.y;
    const int proj = blockIdx.z;

    const float* x    = proj == 0 ? queries : keys;
    const float* W    = proj == 0 ? Wa_w    : Ua_w;
    const float* bias = proj == 0 ? Wa_b    : Ua_b;

    const int t0 = tile * 16;
    __shared__ __align__(16) float xs[16][H];
    __shared__ float sh[H][16];    // for h-pair packing (proj==1)

    const float4* xsrc = (const float4*)(x + (size_t)(b * 512 + t0) * H);
    #pragma unroll
    for (int i = threadIdx.x; i < 16 * H / 4; i += 128)
        ((float4*)xs)[i] = xsrc[i];
    __syncthreads();

    const int h = threadIdx.x;
    float acc[16];
    const float bv = bias[h];
    #pragma unroll
    for (int t = 0; t < 16; t++) acc[t] = bv;

    const float4* Wrow = (const float4*)(W + h * H);
    #pragma unroll 4
    for (int i = 0; i < H / 4; i++) {
        float4 w4 = Wrow[i];
        #pragma unroll
        for (int t = 0; t < 16; t++) {
            float4 xv = ((const float4*)xs[t])[i];
            acc[t] = fmaf(xv.x, w4.x, fmaf(xv.y, w4.y, fmaf(xv.z, w4.z, fmaf(xv.w, w4.w, acc[t]))));
        }
    }

    if (proj == 0) {
        #pragma unroll
        for (int t = 0; t < 16; t++)
            g_qp[(size_t)(b * TQ + t0 + t) * H + h] = acc[t];
    } else {
        #pragma unroll
        for (int t = 0; t < 16; t++) sh[h][t] = acc[t];
        __syncthreads();
        __half2* dst = g_kph + (size_t)b * (H/2) * TK + t0;
        #pragma unroll
        for (int r = 0; r < 8; r++) {
            int idx = threadIdx.x + 128 * r;   // 0..1023
            int t   = idx & 15;
            int j   = idx >> 4;                // h-pair 0..63
            dst[(size_t)j * TK + t] = __floats2half2_rn(sh[2*j][t], sh[2*j+1][t]);
        }
    }
}

// ---------------------------------------------------------------------------
// Kernel 2: scores + softmax (round-6 structure — MUFU-floor measured ~83us).
// grid (TQ/4, B), block 128 (4 warps, 1 q/warp). Lane owns keys {64t+2lane+e}.
// Datapath: HADD2 -> tanh.f16x2 (MUFU) -> HFMA2; f32 flush every 8 h-pairs.
// ---------------------------------------------------------------------------
__global__ void __launch_bounds__(128) score_kernel(
    const float* __restrict__ Va_w,
    float* __restrict__ w_out)     // (B, TQ, TK)
{
    __shared__ __align__(8) float2 qm[4][H/2];   // per warp: {q2 bits, va2 bits}

    const int b    = blockIdx.y;
    const int wid  = threadIdx.x >> 5;
    const int lane = threadIdx.x & 31;
    const int q    = blockIdx.x * 4 + wid;

    {
        const float* qp = g_qp + (size_t)(b * TQ + q) * H;
        #pragma unroll
        for (int r = 0; r < 2; r++) {
            int j = lane + 32 * r;             // h-pair index 0..63
            __half2 q2  = __floats2half2_rn(qp[2*j],   qp[2*j+1]);
            __half2 va2 = __floats2half2_rn(Va_w[2*j], Va_w[2*j+1]);
            qm[wid][j] = make_float2(__uint_as_float(*(unsigned*)&q2),
                                     __uint_as_float(*(unsigned*)&va2));
        }
    }
    __syncwarp();

    float a[16];
    #pragma unroll
    for (int i = 0; i < 16; i++) a[i] = 0.f;

    const uint2* kb = (const uint2*)(g_kph + (size_t)b * (H/2) * TK) + lane;

    #pragma unroll 1
    for (int jb = 0; jb < 8; jb++) {           // 8 blocks of 8 h-pairs
        __half2 acc2[16];
        #pragma unroll
        for (int i = 0; i < 16; i++) acc2[i] = __half2half2(__float2half(0.f));

        #pragma unroll
        for (int j2 = 0; j2 < 8; j2++) {
            int j = jb * 8 + j2;
            float2 meta = qm[wid][j];          // broadcast LDS.64
            unsigned qb = __float_as_uint(meta.x);
            unsigned vb = __float_as_uint(meta.y);
            __half2 q2  = *(__half2*)&qb;
            __half2 va2 = *(__half2*)&vb;

            const uint2* kr = kb + j * (TK / 2);
            uint2 kk[8];
            #pragma unroll
            for (int t = 0; t < 8; t++) kk[t] = kr[t * 32];   // MLP=8 LDG.64
            #pragma unroll
            for (int t = 0; t < 8; t++) {
                __half2 k0 = *(__half2*)&kk[t].x;
                __half2 k1 = *(__half2*)&kk[t].y;
                acc2[2*t]   = __hfma2(va2, tanh2(__hadd2(q2, k0)), acc2[2*t]);
                acc2[2*t+1] = __hfma2(va2, tanh2(__hadd2(q2, k1)), acc2[2*t+1]);
            }
        }
        #pragma unroll
        for (int i = 0; i < 16; i++) {
            float2 f = __half22float2(acc2[i]);
            a[i] += f.x + f.y;                 // fold even/odd-h partial sums
        }
    }

    // ---- softmax in registers ----
    float m = a[0];
    #pragma unroll
    for (int i = 1; i < 16; i++) m = fmaxf(m, a[i]);
    #pragma unroll
    for (int o = 16; o > 0; o >>= 1)
        m = fmaxf(m, __shfl_xor_sync(0xffffffffu, m, o));

    float s = 0.f;
    #pragma unroll
    for (int i = 0; i < 16; i++) { a[i] = __expf(a[i] - m); s += a[i]; }
    #pragma unroll
    for (int o = 16; o > 0; o >>= 1)
        s += __shfl_xor_sync(0xffffffffu, s, o);

    const float inv = __fdividef(1.f, s);
    float* wrow = w_out + (size_t)(b * TQ + q) * TK;
    #pragma unroll
    for (int t = 0; t < 8; t++)
        *(float2*)(wrow + 64 * t + 2 * lane) =
            make_float2(a[2*t] * inv, a[2*t+1] * inv);
}

// ---------------------------------------------------------------------------
// Kernel 3: context = w @ keys. grid (TQ/16, B), block 256 (8 warps, 16 q).
// Keys staged in smem chunks shared by all 8 warps -> L2 traffic halved;
// hot loop = conflict-free LDS.128 + broadcast LDS + 8 FFMA per key.
// ---------------------------------------------------------------------------
__global__ void __launch_bounds__(256) ctx_kernel(
    const float* __restrict__ keys,
    const float* __restrict__ w_in,    // (B, TQ, TK)
    float* __restrict__ ctx_out)       // (B, TQ, H)
{
    __shared__ float  wsm[16][TK];                  // 32 KB weights
    __shared__ __align__(16) float4 skv[32 * 32];   // 16 KB: 32 keys x 128 floats

    const int b    = blockIdx.y;
    const int wid  = threadIdx.x >> 5;
    const int lane = threadIdx.x & 31;
    const int q0   = blockIdx.x * 16 + 2 * wid;

    {   // each warp stages its own 2 weight rows (coalesced)
        const float4* src = (const float4*)(w_in + (size_t)(b * TQ + q0) * TK);
        float4* dst = (float4*)&wsm[2 * wid][0];
        #pragma unroll
        for (int i = 0; i < 8; i++)
            dst[lane + 32 * i] = src[lane + 32 * i];
    }

    float4 acc0 = make_float4(0.f, 0.f, 0.f, 0.f);
    float4 acc1 = make_float4(0.f, 0.f, 0.f, 0.f);
    const float4* ksrc4 = (const float4*)(keys + (size_t)b * TK * H);
    const float* w0 = wsm[2 * wid];
    const float* w1 = wsm[2 * wid + 1];

    #pragma unroll 1
    for (int c = 0; c < 16; c++) {             // 16 chunks of 32 keys
        __syncthreads();                       // prev chunk consumed (+ wsm on c=0)
        #pragma unroll
        for (int r = 0; r < 4; r++) {
            int idx = threadIdx.x + 256 * r;   // 0..1023
            skv[idx] = ksrc4[c * 1024 + idx];
        }
        __syncthreads();

        #pragma unroll 8
        for (int kk = 0; kk < 32; kk++) {
            float4 kv = skv[kk * 32 + lane];   // conflict-free LDS.128
            float  wa = w0[32 * c + kk];       // broadcast LDS
            float  wb = w1[32 * c + kk];
            acc0.x = fmaf(wa, kv.x, acc0.x); acc0.y = fmaf(wa, kv.y, acc0.y);
            acc0.z = fmaf(wa, kv.z, acc0.z); acc0.w = fmaf(wa, kv.w, acc0.w);
            acc1.x = fmaf(wb, kv.x, acc1.x); acc1.y = fmaf(wb, kv.y, acc1.y);
            acc1.z = fmaf(wb, kv.z, acc1.z); acc1.w = fmaf(wb, kv.w, acc1.w);
        }
    }
    float4* crow = (float4*)(ctx_out + (size_t)(b * TQ + q0) * H);
    crow[lane]           = acc0;
    crow[lane + (H / 4)] = acc1;
}

// ---------------------------------------------------------------------------
extern "C" void kernel_launch(void* const* d_in, const int* in_sizes, int n_in,
                              void* d_out, int out_size)
{
    const float* queries = (const float*)d_in[0];
    const float* keys    = (const float*)d_in[1];
    const float* Wa_w    = (const float*)d_in[2];
    const float* Wa_b    = (const float*)d_in[3];
    const float* Ua_w    = (const float*)d_in[4];
    const float* Ua_b    = (const float*)d_in[5];
    const float* Va_w    = (const float*)d_in[6];
    // Va bias (d_in[7]) cancels in softmax -> unused.

    float* ctx_out = (float*)d_out;                     // (B, TQ, H)
    float* w_out   = ctx_out + BATCH * TQ * H;          // (B, TQ, TK)

    dim3 g1(512 / 16, BATCH, 2);
    proj_kernel<<<g1, 128>>>(queries, keys, Wa_w, Wa_b, Ua_w, Ua_b);

    dim3 g2(TQ / 4, BATCH);
    score_kernel<<<g2, 128>>>(Va_w, w_out);

    dim3 g3(TQ / 16, BATCH);
    ctx_kernel<<<g3, 256>>>(keys, w_out, ctx_out);
}

// round 11
// speedup vs baseline: 1.1866x; 1.0003x over previous
#include <cuda_runtime.h>
#include <cuda_bf16.h>
#include <cuda_fp16.h>

#define H     128
#define BATCH 8
#define TQ    512
#define TK    512

// Device scratch (allocation-free rule: __device__ globals)
__device__ __align__(16) __half2 g_kph[BATCH * (H/2) * TK];  // [b][h/2][k] packed h-pairs
__device__ __align__(16) float   g_WaT[H * H];               // Wa transposed: WaT[k][h]

__device__ __forceinline__ __half2 tanh2(__half2 x) {
    unsigned xi = *(unsigned*)&x, yi;
    asm("tanh.approx.f16x2 %0, %1;" : "=r"(yi) : "r"(xi));
    return *(__half2*)&yi;
}

// ---------------------------------------------------------------------------
// Kernel 1: prep.
//   z==0: k-projection  g_kph[b][h/2][t] = keys @ Ua_w^T + Ua_b  (half2 pairs)
//         (round-6 structure — best measured)
//   z==1: transpose Wa into g_WaT (only blocks with b==0 active; ~64KB total)
// grid = (32, B, 2), block = 128
// ---------------------------------------------------------------------------
__global__ void __launch_bounds__(128) prep_kernel(
    const float* __restrict__ keys,
    const float* __restrict__ Ua_w, const float* __restrict__ Ua_b,
    const float* __restrict__ Wa_w)
{
    const int tile = blockIdx.x;   // 32 tiles of 16 rows
    const int b    = blockIdx.y;

    if (blockIdx.z == 1) {
        if (b != 0) return;
        // Transpose 4 rows of Wa: coalesced reads, scattered stores (fire&forget)
        const int r0 = tile * 4;
        #pragma unroll
        for (int i = threadIdx.x; i < 4 * H; i += 128) {
            int r = i >> 7, c = i & 127;
            g_WaT[(size_t)c * H + r0 + r] = Wa_w[(size_t)(r0 + r) * H + c];
        }
        return;
    }

    const int t0 = tile * 16;
    __shared__ __align__(16) float xs[16][H];
    __shared__ float sh[H][16];    // for h-pair packing

    const float4* xsrc = (const float4*)(keys + (size_t)(b * 512 + t0) * H);
    #pragma unroll
    for (int i = threadIdx.x; i < 16 * H / 4; i += 128)
        ((float4*)xs)[i] = xsrc[i];
    __syncthreads();

    const int h = threadIdx.x;
    float acc[16];
    const float bv = Ua_b[h];
    #pragma unroll
    for (int t = 0; t < 16; t++) acc[t] = bv;

    const float4* Wrow = (const float4*)(Ua_w + h * H);
    #pragma unroll 4
    for (int i = 0; i < H / 4; i++) {
        float4 w4 = Wrow[i];
        #pragma unroll
        for (int t = 0; t < 16; t++) {
            float4 xv = ((const float4*)xs[t])[i];
            acc[t] = fmaf(xv.x, w4.x, fmaf(xv.y, w4.y, fmaf(xv.z, w4.z, fmaf(xv.w, w4.w, acc[t]))));
        }
    }

    #pragma unroll
    for (int t = 0; t < 16; t++) sh[h][t] = acc[t];
    __syncthreads();
    __half2* dst = g_kph + (size_t)b * (H/2) * TK + t0;
    #pragma unroll
    for (int r = 0; r < 8; r++) {
        int idx = threadIdx.x + 128 * r;   // 0..1023
        int t   = idx & 15;
        int j   = idx >> 4;                // h-pair 0..63
        dst[(size_t)j * TK + t] = __floats2half2_rn(sh[2*j][t], sh[2*j+1][t]);
    }
}

// ---------------------------------------------------------------------------
// Kernel 2: FUSED q-projection + scores + softmax.
// grid (TQ/4, B), block 128 (4 warps, 1 q/warp).
// Prologue: each warp computes its q-row projection via coalesced WaT reads
// (fma/LSU pipes — idle during the MUFU-bound hot loop of co-resident blocks).
// Hot loop: round-6 datapath (HADD2 -> tanh.f16x2 -> HFMA2, f32 flush /8).
// ---------------------------------------------------------------------------
__global__ void __launch_bounds__(128) score_kernel(
    const float* __restrict__ queries,
    const float* __restrict__ Wa_b,
    const float* __restrict__ Va_w,
    float* __restrict__ w_out)     // (B, TQ, TK)
{
    __shared__ __align__(16) float  qs[4][H];    // 2 KB raw query rows
    __shared__ __align__(8)  float2 qm[4][H/2];  // per warp: {q2 bits, va2 bits}

    const int b    = blockIdx.y;
    const int wid  = threadIdx.x >> 5;
    const int lane = threadIdx.x & 31;
    const int q    = blockIdx.x * 4 + wid;

    // Stage 4 query rows (coalesced: 128 float4 = 512 floats)
    ((float4*)qs)[threadIdx.x] =
        ((const float4*)(queries + (size_t)(b * TQ + blockIdx.x * 4) * H))[threadIdx.x];
    __syncthreads();

    // ---- Fused q-projection: qp[4lane..4lane+3] = q-row @ Wa^T + b ----
    float4 acc = ((const float4*)Wa_b)[lane];
    {
        const float*  qrow = qs[wid];
        const float4* WT   = (const float4*)g_WaT + lane;   // WaT[k][4lane..+3]
        #pragma unroll 8
        for (int k = 0; k < H; k++) {
            float  xk = qrow[k];        // broadcast LDS
            float4 wv = WT[k * 32];     // coalesced LDG.128, L1-hot
            acc.x = fmaf(xk, wv.x, acc.x);
            acc.y = fmaf(xk, wv.y, acc.y);
            acc.z = fmaf(xk, wv.z, acc.z);
            acc.w = fmaf(xk, wv.w, acc.w);
        }
    }
    {
        __half2 q2a = __floats2half2_rn(acc.x, acc.y);
        __half2 q2b = __floats2half2_rn(acc.z, acc.w);
        float4  vv  = ((const float4*)Va_w)[lane];
        __half2 va0 = __floats2half2_rn(vv.x, vv.y);
        __half2 va1 = __floats2half2_rn(vv.z, vv.w);
        qm[wid][2*lane]   = make_float2(__uint_as_float(*(unsigned*)&q2a),
                                        __uint_as_float(*(unsigned*)&va0));
        qm[wid][2*lane+1] = make_float2(__uint_as_float(*(unsigned*)&q2b),
                                        __uint_as_float(*(unsigned*)&va1));
    }
    __syncwarp();

    // ---- Hot loop: scores over 512 keys (lane owns keys 64t + 2lane + e) ----
    float a[16];
    #pragma unroll
    for (int i = 0; i < 16; i++) a[i] = 0.f;

    const uint2* kb = (const uint2*)(g_kph + (size_t)b * (H/2) * TK) + lane;

    #pragma unroll 1
    for (int jb = 0; jb < 8; jb++) {           // 8 blocks of 8 h-pairs
        __half2 acc2[16];
        #pragma unroll
        for (int i = 0; i < 16; i++) acc2[i] = __half2half2(__float2half(0.f));

        #pragma unroll
        for (int j2 = 0; j2 < 8; j2++) {
            int j = jb * 8 + j2;
            float2 meta = qm[wid][j];          // broadcast LDS.64
            unsigned qb2 = __float_as_uint(meta.x);
            unsigned vb2 = __float_as_uint(meta.y);
            __half2 q2  = *(__half2*)&qb2;
            __half2 va2 = *(__half2*)&vb2;

            const uint2* kr = kb + j * (TK / 2);
            uint2 kk[8];
            #pragma unroll
            for (int t = 0; t < 8; t++) kk[t] = kr[t * 32];   // MLP=8 LDG.64
            #pragma unroll
            for (int t = 0; t < 8; t++) {
                __half2 k0 = *(__half2*)&kk[t].x;
                __half2 k1 = *(__half2*)&kk[t].y;
                acc2[2*t]   = __hfma2(va2, tanh2(__hadd2(q2, k0)), acc2[2*t]);
                acc2[2*t+1] = __hfma2(va2, tanh2(__hadd2(q2, k1)), acc2[2*t+1]);
            }
        }
        #pragma unroll
        for (int i = 0; i < 16; i++) {
            float2 f = __half22float2(acc2[i]);
            a[i] += f.x + f.y;                 // fold even/odd-h partial sums
        }
    }

    // ---- softmax in registers ----
    float m = a[0];
    #pragma unroll
    for (int i = 1; i < 16; i++) m = fmaxf(m, a[i]);
    #pragma unroll
    for (int o = 16; o > 0; o >>= 1)
        m = fmaxf(m, __shfl_xor_sync(0xffffffffu, m, o));

    float s = 0.f;
    #pragma unroll
    for (int i = 0; i < 16; i++) { a[i] = __expf(a[i] - m); s += a[i]; }
    #pragma unroll
    for (int o = 16; o > 0; o >>= 1)
        s += __shfl_xor_sync(0xffffffffu, s, o);

    const float inv = __fdividef(1.f, s);
    float* wrow = w_out + (size_t)(b * TQ + q) * TK;
    #pragma unroll
    for (int t = 0; t < 8; t++)
        *(float2*)(wrow + 64 * t + 2 * lane) =
            make_float2(a[2*t] * inv, a[2*t+1] * inv);
}

// ---------------------------------------------------------------------------
// Kernel 3: context = w @ keys (round-6 per-warp streaming — best measured).
// grid (TQ/8, B), block 128 (4 warps). Two queries per warp.
// ---------------------------------------------------------------------------
__global__ void __launch_bounds__(128) ctx_kernel(
    const float* __restrict__ keys,
    const float* __restrict__ w_in,    // (B, TQ, TK)
    float* __restrict__ ctx_out)       // (B, TQ, H)
{
    __shared__ float wsm[8][TK];

    const int b    = blockIdx.y;
    const int wid  = threadIdx.x >> 5;
    const int lane = threadIdx.x & 31;
    const int q0   = blockIdx.x * 8 + 2 * wid;

    {
        const float4* src = (const float4*)(w_in + (size_t)(b * TQ + q0) * TK);
        float4* dst = (float4*)&wsm[2 * wid][0];
        #pragma unroll
        for (int i = 0; i < 8; i++)
            dst[lane + 32 * i] = src[lane + 32 * i];
    }
    __syncwarp();

    float4 acc0 = make_float4(0.f, 0.f, 0.f, 0.f);
    float4 acc1 = make_float4(0.f, 0.f, 0.f, 0.f);
    const float4* kb = (const float4*)(keys + (size_t)b * TK * H) + lane;
    const float* w0 = wsm[2 * wid];
    const float* w1 = wsm[2 * wid + 1];
    #pragma unroll 8
    for (int key = 0; key < TK; key++) {
        float4 kv = kb[key * (H / 4)];           // coalesced LDG.128, L1/L2-hot
        float wa = w0[key];                      // broadcast LDS
        float wb = w1[key];
        acc0.x = fmaf(wa, kv.x, acc0.x); acc0.y = fmaf(wa, kv.y, acc0.y);
        acc0.z = fmaf(wa, kv.z, acc0.z); acc0.w = fmaf(wa, kv.w, acc0.w);
        acc1.x = fmaf(wb, kv.x, acc1.x); acc1.y = fmaf(wb, kv.y, acc1.y);
        acc1.z = fmaf(wb, kv.z, acc1.z); acc1.w = fmaf(wb, kv.w, acc1.w);
    }
    float4* crow = (float4*)(ctx_out + (size_t)(b * TQ + q0) * H);
    crow[lane]           = acc0;
    crow[lane + (H / 4)] = acc1;
}

// ---------------------------------------------------------------------------
extern "C" void kernel_launch(void* const* d_in, const int* in_sizes, int n_in,
                              void* d_out, int out_size)
{
    const float* queries = (const float*)d_in[0];
    const float* keys    = (const float*)d_in[1];
    const float* Wa_w    = (const float*)d_in[2];
    const float* Wa_b    = (const float*)d_in[3];
    const float* Ua_w    = (const float*)d_in[4];
    const float* Ua_b    = (const float*)d_in[5];
    const float* Va_w    = (const float*)d_in[6];
    // Va bias (d_in[7]) cancels in softmax -> unused.

    float* ctx_out = (float*)d_out;                     // (B, TQ, H)
    float* w_out   = ctx_out + BATCH * TQ * H;          // (B, TQ, TK)

    dim3 g1(32, BATCH, 2);
    prep_kernel<<<g1, 128>>>(keys, Ua_w, Ua_b, Wa_w);

    dim3 g2(TQ / 4, BATCH);
    score_kernel<<<g2, 128>>>(queries, Wa_b, Va_w, w_out);

    dim3 g3(TQ / 8, BATCH);
    ctx_kernel<<<g3, 128>>>(keys, w_out, ctx_out);
}